// round 8
// baseline (speedup 1.0000x reference)
#include <cuda_runtime.h>
#include <cuda_bf16.h>
#include <cuda_fp16.h>
#include <cstdint>

// Problem constants (match reference)
#define NN      100000      // nodes
#define EE      800000      // edges (pre self-loop)
#define EPMAX   (EE + NN)   // edges + self loops
#define GD      128         // feature dim
#define NGRAPH  256

// -------------------- device scratch (no allocs allowed) --------------------
__device__ __half g_bufHh[NN * GD]; // h = in @ W  (fp16 gather source)
__device__ float g_buf1[NN * GD];   // layer outputs (ping)
__device__ float g_buf2[NN * GD];   // layer outputs (pong)
__device__ float g_as[NN];
__device__ float g_ad[NN];
__device__ int   g_deg[NN];         // edge histogram (zeroed by scan_fused each pass)
__device__ int   g_start[NN];       // CSR row offsets (exclusive scan)
__device__ int   g_cursor[NN];      // fill cursors -> row ends after csr_fill
__device__ int   g_csr[EPMAX];      // src node id per (dst-sorted) edge

// -------------------- CSR build (3 kernels) --------------------
// 1) histogram incoming edges into g_deg (g_deg is zero before every call:
//    zero-initialized at module load; re-zeroed inside scan_fused each pass)
__global__ void hist_edges(const int* __restrict__ ei, int E) {
    int e = blockIdx.x * blockDim.x + threadIdx.x;
    if (e < E) atomicAdd(&g_deg[ei[E + e]], 1);
}

// 2) single-block chunked exclusive scan of (g_deg[i] + 1)  [+1 = self loop]
//    writes g_start/g_cursor, and zeroes g_deg for the next replay.
__global__ __launch_bounds__(1024) void scan_fused(int Nn) {
    __shared__ int sm[1024];
    const int tid = threadIdx.x;
    const int CH = (Nn + 1023) >> 10;            // chunk per thread
    const int b = tid * CH;
    const int e = min(b + CH, Nn);

    // pass A: thread-local sum
    int s = 0;
    for (int i = b; i < e; i++) s += g_deg[i] + 1;
    sm[tid] = s;
    __syncthreads();
    // block inclusive scan (Hillis-Steele)
    #pragma unroll
    for (int off = 1; off < 1024; off <<= 1) {
        int t = (tid >= off) ? sm[tid - off] : 0;
        __syncthreads();
        sm[tid] += t;
        __syncthreads();
    }
    int run = sm[tid] - s;                        // exclusive prefix for this thread
    // pass B: write offsets, zero histogram
    for (int i = b; i < e; i++) {
        int v = g_deg[i] + 1;
        g_start[i]  = run;
        g_cursor[i] = run;
        g_deg[i] = 0;
        run += v;
    }
}

// 3) scatter edges into dst-sorted CSR
__global__ void csr_fill(const int* __restrict__ ei, int E, int Nn) {
    int e = blockIdx.x * blockDim.x + threadIdx.x;
    int total = E + Nn;
    if (e >= total) return;
    int s, d;
    if (e < E) { s = ei[e]; d = ei[E + e]; }
    else       { s = d = e - E; }
    int idx = atomicAdd(&g_cursor[d], 1);
    g_csr[idx] = s;
}

// -------------------- mma.sync bf16 GEMM + fused attn epilogue --------------------
// 3-term split: H = Ah*Bh + Al*Bh + Ah*Bl (bf16 inputs, fp32 accum).
// Epilogue: store h as fp16 AND compute g_as/g_ad = h . a_src / h . a_dst in-register.
#define PK32    68                        // padded K stride in u32 units (136 bf16)
#define TILE32  (128 * PK32)              // u32 per tile = 8704
#define ATTN_OFF (4 * TILE32)
#define GEMM_SMEM_BYTES ((4 * TILE32 + 512) * 4)  // 141312

__device__ __forceinline__ void mma16816(float* c, const uint32_t* a, const uint32_t* b) {
    asm volatile(
        "mma.sync.aligned.m16n8k16.row.col.f32.bf16.bf16.f32 "
        "{%0,%1,%2,%3}, {%4,%5,%6,%7}, {%8,%9}, {%0,%1,%2,%3};"
        : "+f"(c[0]), "+f"(c[1]), "+f"(c[2]), "+f"(c[3])
        : "r"(a[0]), "r"(a[1]), "r"(a[2]), "r"(a[3]), "r"(b[0]), "r"(b[1]));
}

__device__ __forceinline__ uint32_t pack_hi(float x, float y, uint32_t& lo) {
    __nv_bfloat16 hx = __float2bfloat16(x);
    __nv_bfloat16 hy = __float2bfloat16(y);
    __nv_bfloat16 lx = __float2bfloat16(x - __bfloat162float(hx));
    __nv_bfloat16 ly = __float2bfloat16(y - __bfloat162float(hy));
    __nv_bfloat162 hp; hp.x = hx; hp.y = hy;
    __nv_bfloat162 lp; lp.x = lx; lp.y = ly;
    lo = *(uint32_t*)&lp;
    return *(uint32_t*)&hp;
}

__global__ __launch_bounds__(256) void gemm_mma(const float* __restrict__ Xin,
                                                const float* __restrict__ W,
                                                const float* __restrict__ a_src,
                                                const float* __restrict__ a_dst,
                                                int sel, int M) {
    extern __shared__ uint32_t sm32[];
    uint32_t* As_hi = sm32;
    uint32_t* As_lo = sm32 + TILE32;
    uint32_t* Bs_hi = sm32 + 2 * TILE32;
    uint32_t* Bs_lo = sm32 + 3 * TILE32;
    float* s_asrc = (float*)(sm32 + ATTN_OFF);
    float* s_adst = s_asrc + 128;
    float* s_ps   = s_asrc + 256;
    float* s_pd   = s_asrc + 384;

    const float* X = (sel == 0) ? Xin : ((sel == 1) ? g_buf1 : g_buf2);
    const int tid  = threadIdx.x;
    const int wid  = tid >> 5;
    const int lane = tid & 31;
    const int m0   = blockIdx.x * 128;

    if (tid < 128) {
        s_asrc[tid] = __ldg(a_src + tid);
        s_adst[tid] = __ldg(a_dst + tid);
    }

    // ---- fill A tile (X rows m0..m0+127), split hi/lo ----
    #pragma unroll
    for (int i = 0; i < 32; i++) {
        int idx = i * 256 + tid;       // 0..8191
        int r   = idx >> 6;            // 0..127
        int c2  = idx & 63;            // u32 col
        float ax = 0.f, ay = 0.f;
        if (m0 + r < M) {
            float2 v = *(const float2*)(X + (size_t)(m0 + r) * GD + 2 * c2);
            ax = v.x; ay = v.y;
        }
        uint32_t lo, hi = pack_hi(ax, ay, lo);
        As_hi[r * PK32 + c2] = hi;
        As_lo[r * PK32 + c2] = lo;
    }
    // ---- fill B tile: Bs[n][k] = W[k][n] (col-major of KxN), split hi/lo ----
    #pragma unroll
    for (int i = 0; i < 32; i++) {
        int idx = i * 256 + tid;       // 0..8191
        int n   = idx & 127;           // coalesced over W rows
        int kp  = idx >> 7;            // 0..63
        float a = W[(size_t)(2 * kp) * GD + n];
        float b = W[(size_t)(2 * kp + 1) * GD + n];
        uint32_t lo, hi = pack_hi(a, b, lo);
        Bs_hi[n * PK32 + kp] = hi;
        Bs_lo[n * PK32 + kp] = lo;
    }
    __syncthreads();

    // ---- warp tiling: 4x2 warps, warp tile 32x64 ----
    const int wm = wid & 3;            // m group (32 rows)
    const int wn = wid >> 2;           // n group (64 cols)
    const int g  = lane >> 2;
    const int t  = lane & 3;

    float acc[2][8][4];
    #pragma unroll
    for (int mt = 0; mt < 2; mt++)
        #pragma unroll
        for (int nt = 0; nt < 8; nt++)
            #pragma unroll
            for (int q = 0; q < 4; q++) acc[mt][nt][q] = 0.f;

    #pragma unroll
    for (int ks = 0; ks < 8; ks++) {       // k0 = ks*16, u32 offset = ks*8
        const int kb = ks * 8 + t;
        uint32_t ah[2][4], al[2][4];
        #pragma unroll
        for (int mt = 0; mt < 2; mt++) {
            int R = wm * 32 + mt * 16 + g;
            ah[mt][0] = As_hi[R * PK32 + kb];
            ah[mt][1] = As_hi[(R + 8) * PK32 + kb];
            ah[mt][2] = As_hi[R * PK32 + kb + 4];
            ah[mt][3] = As_hi[(R + 8) * PK32 + kb + 4];
            al[mt][0] = As_lo[R * PK32 + kb];
            al[mt][1] = As_lo[(R + 8) * PK32 + kb];
            al[mt][2] = As_lo[R * PK32 + kb + 4];
            al[mt][3] = As_lo[(R + 8) * PK32 + kb + 4];
        }
        uint32_t bh[8][2], bl[8][2];
        #pragma unroll
        for (int nt = 0; nt < 8; nt++) {
            int C = wn * 64 + nt * 8 + g;
            bh[nt][0] = Bs_hi[C * PK32 + kb];
            bh[nt][1] = Bs_hi[C * PK32 + kb + 4];
            bl[nt][0] = Bs_lo[C * PK32 + kb];
            bl[nt][1] = Bs_lo[C * PK32 + kb + 4];
        }
        #pragma unroll
        for (int mt = 0; mt < 2; mt++)
            #pragma unroll
            for (int nt = 0; nt < 8; nt++) {
                mma16816(acc[mt][nt], ah[mt], bh[nt]);
                mma16816(acc[mt][nt], al[mt], bh[nt]);
                mma16816(acc[mt][nt], ah[mt], bl[nt]);
            }
    }

    // ---- epilogue: write fp16 h + fused attention dot products ----
    float ps[4] = {0.f, 0.f, 0.f, 0.f};
    float pd[4] = {0.f, 0.f, 0.f, 0.f};
    #pragma unroll
    for (int mt = 0; mt < 2; mt++) {
        int r0 = m0 + wm * 32 + mt * 16 + g;
        #pragma unroll
        for (int nt = 0; nt < 8; nt++) {
            int cc = wn * 64 + nt * 8 + 2 * t;
            float a0 = s_asrc[cc], a1 = s_asrc[cc + 1];
            float d0 = s_adst[cc], d1 = s_adst[cc + 1];
            ps[mt * 2 + 0] += acc[mt][nt][0] * a0 + acc[mt][nt][1] * a1;
            ps[mt * 2 + 1] += acc[mt][nt][2] * a0 + acc[mt][nt][3] * a1;
            pd[mt * 2 + 0] += acc[mt][nt][0] * d0 + acc[mt][nt][1] * d1;
            pd[mt * 2 + 1] += acc[mt][nt][2] * d0 + acc[mt][nt][3] * d1;
            if (r0 < M)
                *(__half2*)(g_bufHh + (size_t)r0 * GD + cc) =
                    __floats2half2_rn(acc[mt][nt][0], acc[mt][nt][1]);
            if (r0 + 8 < M)
                *(__half2*)(g_bufHh + (size_t)(r0 + 8) * GD + cc) =
                    __floats2half2_rn(acc[mt][nt][2], acc[mt][nt][3]);
        }
    }
    #pragma unroll
    for (int q = 0; q < 4; q++) {
        ps[q] += __shfl_xor_sync(0xFFFFFFFFu, ps[q], 1);
        ps[q] += __shfl_xor_sync(0xFFFFFFFFu, ps[q], 2);
        pd[q] += __shfl_xor_sync(0xFFFFFFFFu, pd[q], 1);
        pd[q] += __shfl_xor_sync(0xFFFFFFFFu, pd[q], 2);
    }
    if (wn == 0 && t == 0) {
        #pragma unroll
        for (int q = 0; q < 4; q++) {
            int local = wm * 32 + (q >> 1) * 16 + (q & 1) * 8 + g;
            s_ps[local] = ps[q];
            s_pd[local] = pd[q];
        }
    }
    __syncthreads();
    if (wn == 1 && t == 0) {
        #pragma unroll
        for (int q = 0; q < 4; q++) {
            int local = wm * 32 + (q >> 1) * 16 + (q & 1) * 8 + g;
            int m = m0 + local;
            if (m < M) {
                g_as[m] = s_ps[local] + ps[q];
                g_ad[m] = s_pd[local] + pd[q];
            }
        }
    }
}

// -------------------- fused softmax + aggregate + bias (warp per dst) --------------------
__global__ void aggregate(const float* __restrict__ bias, int sel, int Nn) {
    int d = (blockIdx.x * blockDim.x + threadIdx.x) >> 5;
    int lane = threadIdx.x & 31;
    if (d >= Nn) return;
    float* OUT = (sel == 1) ? g_buf2 : g_buf1;   // 0->buf1, 1->buf2, 2->buf1

    int beg = g_start[d];
    int end = g_cursor[d];          // row end (cursor settled after csr_fill)
    float adv = g_ad[d];

    // pass 1: max logit (lanes parallel over edges)
    float mx = -3.0e38f;
    for (int i = beg + lane; i < end; i += 32) {
        float l = g_as[g_csr[i]] + adv;
        l = l > 0.0f ? l : 0.2f * l;
        mx = fmaxf(mx, l);
    }
    #pragma unroll
    for (int off = 16; off; off >>= 1)
        mx = fmaxf(mx, __shfl_xor_sync(0xFFFFFFFFu, mx, off));

    // pass 2: exp, denom, weighted fp16 gather-accumulate (4-way unrolled for MLP)
    float denom = 0.0f;
    float4 acc = make_float4(0.f, 0.f, 0.f, 0.f);
    int i = beg;
    for (; i + 4 <= end; i += 4) {
        int s0 = g_csr[i], s1 = g_csr[i + 1], s2 = g_csr[i + 2], s3 = g_csr[i + 3];
        float l0 = g_as[s0] + adv;
        float l1 = g_as[s1] + adv;
        float l2 = g_as[s2] + adv;
        float l3 = g_as[s3] + adv;
        uint2 r0 = *(const uint2*)(g_bufHh + (size_t)s0 * GD + lane * 4);
        uint2 r1 = *(const uint2*)(g_bufHh + (size_t)s1 * GD + lane * 4);
        uint2 r2 = *(const uint2*)(g_bufHh + (size_t)s2 * GD + lane * 4);
        uint2 r3 = *(const uint2*)(g_bufHh + (size_t)s3 * GD + lane * 4);
        l0 = l0 > 0.0f ? l0 : 0.2f * l0;
        l1 = l1 > 0.0f ? l1 : 0.2f * l1;
        l2 = l2 > 0.0f ? l2 : 0.2f * l2;
        l3 = l3 > 0.0f ? l3 : 0.2f * l3;
        float v0 = __expf(l0 - mx);
        float v1 = __expf(l1 - mx);
        float v2 = __expf(l2 - mx);
        float v3 = __expf(l3 - mx);
        denom += (v0 + v1) + (v2 + v3);
        float2 a0 = __half22float2(*(__half2*)&r0.x);
        float2 a1 = __half22float2(*(__half2*)&r0.y);
        float2 b0 = __half22float2(*(__half2*)&r1.x);
        float2 b1 = __half22float2(*(__half2*)&r1.y);
        float2 c0 = __half22float2(*(__half2*)&r2.x);
        float2 c1 = __half22float2(*(__half2*)&r2.y);
        float2 e0 = __half22float2(*(__half2*)&r3.x);
        float2 e1 = __half22float2(*(__half2*)&r3.y);
        acc.x = fmaf(v0, a0.x, acc.x); acc.x = fmaf(v1, b0.x, acc.x);
        acc.x = fmaf(v2, c0.x, acc.x); acc.x = fmaf(v3, e0.x, acc.x);
        acc.y = fmaf(v0, a0.y, acc.y); acc.y = fmaf(v1, b0.y, acc.y);
        acc.y = fmaf(v2, c0.y, acc.y); acc.y = fmaf(v3, e0.y, acc.y);
        acc.z = fmaf(v0, a1.x, acc.z); acc.z = fmaf(v1, b1.x, acc.z);
        acc.z = fmaf(v2, c1.x, acc.z); acc.z = fmaf(v3, e1.x, acc.z);
        acc.w = fmaf(v0, a1.y, acc.w); acc.w = fmaf(v1, b1.y, acc.w);
        acc.w = fmaf(v2, c1.y, acc.w); acc.w = fmaf(v3, e1.y, acc.w);
    }
    for (; i < end; i++) {
        int s = g_csr[i];
        float l = g_as[s] + adv;
        l = l > 0.0f ? l : 0.2f * l;
        float v = __expf(l - mx);
        uint2 r = *(const uint2*)(g_bufHh + (size_t)s * GD + lane * 4);
        denom += v;
        float2 a0 = __half22float2(*(__half2*)&r.x);
        float2 a1 = __half22float2(*(__half2*)&r.y);
        acc.x = fmaf(v, a0.x, acc.x);
        acc.y = fmaf(v, a0.y, acc.y);
        acc.z = fmaf(v, a1.x, acc.z);
        acc.w = fmaf(v, a1.y, acc.w);
    }
    float inv = 1.0f / denom;
    float4 b4 = __ldg(((const float4*)bias) + lane);
    float4 o = make_float4(acc.x * inv + b4.x, acc.y * inv + b4.y,
                           acc.z * inv + b4.z, acc.w * inv + b4.w);
    ((float4*)OUT)[(size_t)d * 32 + lane] = o;
}

// -------------------- global mean pool (block per graph, sorted batch) --------------------
__global__ void pool_kernel(const int* __restrict__ batch, float* __restrict__ out, int Nn) {
    int g = blockIdx.x;        // 0..255
    int c = threadIdx.x;       // 0..127
    int lo = 0, hi = Nn;
    while (lo < hi) { int mid = (lo + hi) >> 1; if (batch[mid] < g) lo = mid + 1; else hi = mid; }
    int s0 = lo;
    hi = Nn;
    while (lo < hi) { int mid = (lo + hi) >> 1; if (batch[mid] < g + 1) lo = mid + 1; else hi = mid; }
    int s1 = lo;

    float sum0 = 0.f, sum1 = 0.f, sum2 = 0.f, sum3 = 0.f;
    int n = s0;
    for (; n + 4 <= s1; n += 4) {
        sum0 += g_buf1[(size_t)(n + 0) * GD + c];
        sum1 += g_buf1[(size_t)(n + 1) * GD + c];
        sum2 += g_buf1[(size_t)(n + 2) * GD + c];
        sum3 += g_buf1[(size_t)(n + 3) * GD + c];
    }
    for (; n < s1; n++) sum0 += g_buf1[(size_t)n * GD + c];
    float sum = (sum0 + sum1) + (sum2 + sum3);
    float cnt = (float)(s1 - s0);
    out[g * GD + c] = sum / fmaxf(cnt, 1.0f);
}

// -------------------- launch --------------------
extern "C" void kernel_launch(void* const* d_in, const int* in_sizes, int n_in,
                              void* d_out, int out_size) {
    const float* x     = (const float*)d_in[0];
    const int*   ei    = (const int*)d_in[1];
    const int*   batch = (const int*)d_in[2];
    const int Nn = in_sizes[0] / GD;
    const int E  = in_sizes[1] / 2;
    float* out = (float*)d_out;

    static int smem_set = 0;
    if (!smem_set) {
        cudaFuncSetAttribute(gemm_mma, cudaFuncAttributeMaxDynamicSharedMemorySize, GEMM_SMEM_BYTES);
        smem_set = 1;
    }

    // ---- CSR build (3 launches) ----
    hist_edges<<<(E + 255) / 256, 256>>>(ei, E);
    scan_fused<<<1, 1024>>>(Nn);
    csr_fill<<<(E + Nn + 255) / 256, 256>>>(ei, E, Nn);

    // ---- 3 GAT layers ----
    int gemm_blocks = (Nn + 127) / 128;
    int warp_blocks = (Nn + 7) / 8;   // 1 warp per node, 256 threads/block
    for (int l = 0; l < 3; l++) {
        const float* W  = (const float*)d_in[3 + 4 * l];
        const float* as = (const float*)d_in[4 + 4 * l];
        const float* ad = (const float*)d_in[5 + 4 * l];
        const float* b  = (const float*)d_in[6 + 4 * l];
        gemm_mma<<<gemm_blocks, 256, GEMM_SMEM_BYTES>>>(x, W, as, ad, l, Nn);
        aggregate<<<warp_blocks, 256>>>(b, l, Nn);
    }

    // ---- mean pool (layer-3 output lives in g_buf1) ----
    pool_kernel<<<NGRAPH, GD>>>(batch, out, Nn);
}

// round 9
// speedup vs baseline: 1.5024x; 1.5024x over previous
#include <cuda_runtime.h>
#include <cuda_bf16.h>
#include <cuda_fp16.h>
#include <cstdint>

// Problem constants (match reference)
#define NN      100000      // nodes
#define EE      800000      // edges (pre self-loop)
#define EPMAX   (EE + NN)   // edges + self loops
#define GD      128         // feature dim
#define NGRAPH  256

// -------------------- device scratch (no allocs allowed) --------------------
__device__ __half g_bufHh[NN * GD]; // h = in @ W  (fp16 gather source)
__device__ float g_buf1[NN * GD];   // layer outputs (ping)
__device__ float g_buf2[NN * GD];   // layer outputs (pong)
__device__ float g_as[NN];
__device__ float g_ad[NN];
__device__ int   g_deg[NN];         // in-degree (incl self loop)
__device__ int   g_incl[NN];        // per-block inclusive scan
__device__ int   g_bsum[256];       // block sums
__device__ int   g_start[NN];       // CSR row offsets (exclusive scan)
__device__ int   g_cursor[NN];      // fill cursors
__device__ int   g_csr[EPMAX];      // src node id per (dst-sorted) edge

// -------------------- CSR build (R6-proven 6-kernel form) --------------------
__global__ void hist_init(int Nn) {
    int i = blockIdx.x * blockDim.x + threadIdx.x;
    if (i < Nn) g_deg[i] = 1;   // self loop
}

__global__ void hist_edges(const int* __restrict__ ei, int E) {
    int e = blockIdx.x * blockDim.x + threadIdx.x;
    if (e < E) atomicAdd(&g_deg[ei[E + e]], 1);
}

__global__ void scan_block(int Nn) {
    __shared__ int sm[1024];
    int tid = threadIdx.x;
    int i = blockIdx.x * 1024 + tid;
    int v = (i < Nn) ? g_deg[i] : 0;
    sm[tid] = v;
    __syncthreads();
    #pragma unroll
    for (int off = 1; off < 1024; off <<= 1) {
        int t = (tid >= off) ? sm[tid - off] : 0;
        __syncthreads();
        sm[tid] += t;
        __syncthreads();
    }
    if (i < Nn) g_incl[i] = sm[tid];
    if (tid == 1023) g_bsum[blockIdx.x] = sm[1023];
}

// exclusive scan over block sums (nb <= 128) in one 128-thread block
__global__ void scan_sums(int nb) {
    __shared__ int sm[128];
    int t = threadIdx.x;
    int v = (t < nb) ? g_bsum[t] : 0;
    sm[t] = v;
    __syncthreads();
    #pragma unroll
    for (int off = 1; off < 128; off <<= 1) {
        int u = (t >= off) ? sm[t - off] : 0;
        __syncthreads();
        sm[t] += u;
        __syncthreads();
    }
    if (t < nb) g_bsum[t] = sm[t] - v;   // exclusive
}

__global__ void scan_apply(int Nn) {
    int i = blockIdx.x * 1024 + threadIdx.x;
    if (i < Nn) {
        int st = g_incl[i] - g_deg[i] + g_bsum[blockIdx.x];  // exclusive
        g_start[i]  = st;
        g_cursor[i] = st;
    }
}

__global__ void csr_fill(const int* __restrict__ ei, int E, int Nn) {
    int e = blockIdx.x * blockDim.x + threadIdx.x;
    int total = E + Nn;
    if (e >= total) return;
    int s, d;
    if (e < E) { s = ei[e]; d = ei[E + e]; }
    else       { s = d = e - E; }
    int idx = atomicAdd(&g_cursor[d], 1);
    g_csr[idx] = s;
}

// -------------------- mma.sync bf16 GEMM (64-row tiles, 2 CTAs/SM) --------------------
// 3-term split: H = Ah*Bh + Al*Bh + Ah*Bl (bf16 inputs, fp32 accum).
// Epilogue: store h as fp16 AND compute g_as/g_ad = h . a_src / h . a_dst in-register.
#define PK32    68                        // padded K stride in u32 units (136 bf16)
#define A32     (64 * PK32)               // 4352 u32 per A tile
#define B32     (128 * PK32)              // 8704 u32 per B tile
#define ATTN_OFF (2 * A32 + 2 * B32)      // 26112
#define GEMM_SMEM_BYTES ((ATTN_OFF + 768) * 4)   // 107520 bytes -> 2 CTAs/SM

__device__ __forceinline__ void mma16816(float* c, const uint32_t* a, const uint32_t* b) {
    asm volatile(
        "mma.sync.aligned.m16n8k16.row.col.f32.bf16.bf16.f32 "
        "{%0,%1,%2,%3}, {%4,%5,%6,%7}, {%8,%9}, {%0,%1,%2,%3};"
        : "+f"(c[0]), "+f"(c[1]), "+f"(c[2]), "+f"(c[3])
        : "r"(a[0]), "r"(a[1]), "r"(a[2]), "r"(a[3]), "r"(b[0]), "r"(b[1]));
}

__device__ __forceinline__ uint32_t pack_hi(float x, float y, uint32_t& lo) {
    __nv_bfloat16 hx = __float2bfloat16(x);
    __nv_bfloat16 hy = __float2bfloat16(y);
    __nv_bfloat16 lx = __float2bfloat16(x - __bfloat162float(hx));
    __nv_bfloat16 ly = __float2bfloat16(y - __bfloat162float(hy));
    __nv_bfloat162 hp; hp.x = hx; hp.y = hy;
    __nv_bfloat162 lp; lp.x = lx; lp.y = ly;
    lo = *(uint32_t*)&lp;
    return *(uint32_t*)&hp;
}

__global__ __launch_bounds__(256, 2) void gemm_mma(const float* __restrict__ Xin,
                                                   const float* __restrict__ W,
                                                   const float* __restrict__ a_src,
                                                   const float* __restrict__ a_dst,
                                                   int sel, int M) {
    extern __shared__ uint32_t sm32[];
    uint32_t* As_hi = sm32;
    uint32_t* As_lo = sm32 + A32;
    uint32_t* Bs_hi = sm32 + 2 * A32;
    uint32_t* Bs_lo = sm32 + 2 * A32 + B32;
    float* s_asrc = (float*)(sm32 + ATTN_OFF);
    float* s_adst = s_asrc + 128;
    float* s_ps   = s_asrc + 256;     // [4 wn][64 rows]
    float* s_pd   = s_asrc + 512;     // [4 wn][64 rows]

    const float* X = (sel == 0) ? Xin : ((sel == 1) ? g_buf1 : g_buf2);
    const int tid  = threadIdx.x;
    const int wid  = tid >> 5;
    const int lane = tid & 31;
    const int m0   = blockIdx.x * 64;

    if (tid < 128) {
        s_asrc[tid] = __ldg(a_src + tid);
        s_adst[tid] = __ldg(a_dst + tid);
    }

    // ---- fill A tile (X rows m0..m0+63), split hi/lo: 4096 u32, 16 iters ----
    #pragma unroll
    for (int i = 0; i < 16; i++) {
        int idx = i * 256 + tid;       // 0..4095
        int r   = idx >> 6;            // 0..63
        int c2  = idx & 63;            // u32 col
        float ax = 0.f, ay = 0.f;
        if (m0 + r < M) {
            float2 v = *(const float2*)(X + (size_t)(m0 + r) * GD + 2 * c2);
            ax = v.x; ay = v.y;
        }
        uint32_t lo, hi = pack_hi(ax, ay, lo);
        As_hi[r * PK32 + c2] = hi;
        As_lo[r * PK32 + c2] = lo;
    }
    // ---- fill B tile: Bs[n][k] = W[k][n] (col-major of KxN), split hi/lo ----
    #pragma unroll
    for (int i = 0; i < 32; i++) {
        int idx = i * 256 + tid;       // 0..8191
        int n   = idx & 127;           // coalesced over W rows
        int kp  = idx >> 7;            // 0..63
        float a = W[(size_t)(2 * kp) * GD + n];
        float b = W[(size_t)(2 * kp + 1) * GD + n];
        uint32_t lo, hi = pack_hi(a, b, lo);
        Bs_hi[n * PK32 + kp] = hi;
        Bs_lo[n * PK32 + kp] = lo;
    }
    __syncthreads();

    // ---- warp tiling: 2x4 warps, warp tile 32x32 ----
    const int wm = wid & 1;            // m group (32 rows)
    const int wn = wid >> 1;           // n group (32 cols), 0..3
    const int g  = lane >> 2;
    const int t  = lane & 3;

    float acc[2][4][4];
    #pragma unroll
    for (int mt = 0; mt < 2; mt++)
        #pragma unroll
        for (int nt = 0; nt < 4; nt++)
            #pragma unroll
            for (int q = 0; q < 4; q++) acc[mt][nt][q] = 0.f;

    #pragma unroll
    for (int ks = 0; ks < 8; ks++) {       // k0 = ks*16, u32 offset = ks*8
        const int kb = ks * 8 + t;
        uint32_t ah[2][4], al[2][4];
        #pragma unroll
        for (int mt = 0; mt < 2; mt++) {
            int R = wm * 32 + mt * 16 + g;
            ah[mt][0] = As_hi[R * PK32 + kb];
            ah[mt][1] = As_hi[(R + 8) * PK32 + kb];
            ah[mt][2] = As_hi[R * PK32 + kb + 4];
            ah[mt][3] = As_hi[(R + 8) * PK32 + kb + 4];
            al[mt][0] = As_lo[R * PK32 + kb];
            al[mt][1] = As_lo[(R + 8) * PK32 + kb];
            al[mt][2] = As_lo[R * PK32 + kb + 4];
            al[mt][3] = As_lo[(R + 8) * PK32 + kb + 4];
        }
        uint32_t bh[4][2], bl[4][2];
        #pragma unroll
        for (int nt = 0; nt < 4; nt++) {
            int C = wn * 32 + nt * 8 + g;
            bh[nt][0] = Bs_hi[C * PK32 + kb];
            bh[nt][1] = Bs_hi[C * PK32 + kb + 4];
            bl[nt][0] = Bs_lo[C * PK32 + kb];
            bl[nt][1] = Bs_lo[C * PK32 + kb + 4];
        }
        #pragma unroll
        for (int mt = 0; mt < 2; mt++)
            #pragma unroll
            for (int nt = 0; nt < 4; nt++) {
                mma16816(acc[mt][nt], ah[mt], bh[nt]);
                mma16816(acc[mt][nt], al[mt], bh[nt]);
                mma16816(acc[mt][nt], ah[mt], bl[nt]);
            }
    }

    // ---- epilogue: write fp16 h + fused attention dot products ----
    float ps[4] = {0.f, 0.f, 0.f, 0.f};   // q = mt*2 + half
    float pd[4] = {0.f, 0.f, 0.f, 0.f};
    #pragma unroll
    for (int mt = 0; mt < 2; mt++) {
        int r0 = m0 + wm * 32 + mt * 16 + g;
        #pragma unroll
        for (int nt = 0; nt < 4; nt++) {
            int cc = wn * 32 + nt * 8 + 2 * t;
            float a0 = s_asrc[cc], a1 = s_asrc[cc + 1];
            float d0 = s_adst[cc], d1 = s_adst[cc + 1];
            ps[mt * 2 + 0] += acc[mt][nt][0] * a0 + acc[mt][nt][1] * a1;
            ps[mt * 2 + 1] += acc[mt][nt][2] * a0 + acc[mt][nt][3] * a1;
            pd[mt * 2 + 0] += acc[mt][nt][0] * d0 + acc[mt][nt][1] * d1;
            pd[mt * 2 + 1] += acc[mt][nt][2] * d0 + acc[mt][nt][3] * d1;
            if (r0 < M)
                *(__half2*)(g_bufHh + (size_t)r0 * GD + cc) =
                    __floats2half2_rn(acc[mt][nt][0], acc[mt][nt][1]);
            if (r0 + 8 < M)
                *(__half2*)(g_bufHh + (size_t)(r0 + 8) * GD + cc) =
                    __floats2half2_rn(acc[mt][nt][2], acc[mt][nt][3]);
        }
    }
    #pragma unroll
    for (int q = 0; q < 4; q++) {
        ps[q] += __shfl_xor_sync(0xFFFFFFFFu, ps[q], 1);
        ps[q] += __shfl_xor_sync(0xFFFFFFFFu, ps[q], 2);
        pd[q] += __shfl_xor_sync(0xFFFFFFFFu, pd[q], 1);
        pd[q] += __shfl_xor_sync(0xFFFFFFFFu, pd[q], 2);
    }
    // each warp stores its 32 rows into its wn slot; then 4-way sum across wn
    if (t == 0) {
        #pragma unroll
        for (int q = 0; q < 4; q++) {
            int local = wm * 32 + (q >> 1) * 16 + (q & 1) * 8 + g;
            s_ps[wn * 64 + local] = ps[q];
            s_pd[wn * 64 + local] = pd[q];
        }
    }
    __syncthreads();
    if (tid < 64) {
        int m = m0 + tid;
        if (m < M) {
            g_as[m] = (s_ps[tid] + s_ps[64 + tid]) + (s_ps[128 + tid] + s_ps[192 + tid]);
            g_ad[m] = (s_pd[tid] + s_pd[64 + tid]) + (s_pd[128 + tid] + s_pd[192 + tid]);
        }
    }
}

// -------------------- fused softmax + aggregate + bias (warp per dst) --------------------
__global__ void aggregate(const float* __restrict__ bias, int sel, int Nn) {
    int d = (blockIdx.x * blockDim.x + threadIdx.x) >> 5;
    int lane = threadIdx.x & 31;
    if (d >= Nn) return;
    float* OUT = (sel == 1) ? g_buf2 : g_buf1;   // 0->buf1, 1->buf2, 2->buf1

    int beg = g_start[d];
    int end = beg + g_deg[d];
    float adv = g_ad[d];

    // pass 1: max logit (lanes parallel over edges)
    float mx = -3.0e38f;
    for (int i = beg + lane; i < end; i += 32) {
        float l = g_as[g_csr[i]] + adv;
        l = l > 0.0f ? l : 0.2f * l;
        mx = fmaxf(mx, l);
    }
    #pragma unroll
    for (int off = 16; off; off >>= 1)
        mx = fmaxf(mx, __shfl_xor_sync(0xFFFFFFFFu, mx, off));

    // pass 2: exp, denom, weighted fp16 gather-accumulate (2-way unrolled for MLP)
    float denom = 0.0f;
    float4 acc = make_float4(0.f, 0.f, 0.f, 0.f);
    int i = beg;
    for (; i + 2 <= end; i += 2) {
        int s0 = g_csr[i];
        int s1 = g_csr[i + 1];
        float l0 = g_as[s0] + adv;
        float l1 = g_as[s1] + adv;
        uint2 r0 = *(const uint2*)(g_bufHh + (size_t)s0 * GD + lane * 4);
        uint2 r1 = *(const uint2*)(g_bufHh + (size_t)s1 * GD + lane * 4);
        l0 = l0 > 0.0f ? l0 : 0.2f * l0;
        l1 = l1 > 0.0f ? l1 : 0.2f * l1;
        float v0 = __expf(l0 - mx);
        float v1 = __expf(l1 - mx);
        denom += v0 + v1;
        float2 a0 = __half22float2(*(__half2*)&r0.x);
        float2 a1 = __half22float2(*(__half2*)&r0.y);
        float2 b0 = __half22float2(*(__half2*)&r1.x);
        float2 b1 = __half22float2(*(__half2*)&r1.y);
        acc.x = fmaf(v0, a0.x, acc.x); acc.x = fmaf(v1, b0.x, acc.x);
        acc.y = fmaf(v0, a0.y, acc.y); acc.y = fmaf(v1, b0.y, acc.y);
        acc.z = fmaf(v0, a1.x, acc.z); acc.z = fmaf(v1, b1.x, acc.z);
        acc.w = fmaf(v0, a1.y, acc.w); acc.w = fmaf(v1, b1.y, acc.w);
    }
    for (; i < end; i++) {
        int s = g_csr[i];
        float l = g_as[s] + adv;
        l = l > 0.0f ? l : 0.2f * l;
        float v = __expf(l - mx);
        uint2 r = *(const uint2*)(g_bufHh + (size_t)s * GD + lane * 4);
        denom += v;
        float2 a0 = __half22float2(*(__half2*)&r.x);
        float2 a1 = __half22float2(*(__half2*)&r.y);
        acc.x = fmaf(v, a0.x, acc.x);
        acc.y = fmaf(v, a0.y, acc.y);
        acc.z = fmaf(v, a1.x, acc.z);
        acc.w = fmaf(v, a1.y, acc.w);
    }
    float inv = 1.0f / denom;
    float4 b4 = __ldg(((const float4*)bias) + lane);
    float4 o = make_float4(acc.x * inv + b4.x, acc.y * inv + b4.y,
                           acc.z * inv + b4.z, acc.w * inv + b4.w);
    ((float4*)OUT)[(size_t)d * 32 + lane] = o;
}

// -------------------- global mean pool (block per graph, sorted batch) --------------------
__global__ void pool_kernel(const int* __restrict__ batch, float* __restrict__ out, int Nn) {
    int g = blockIdx.x;        // 0..255
    int c = threadIdx.x;       // 0..127
    int lo = 0, hi = Nn;
    while (lo < hi) { int mid = (lo + hi) >> 1; if (batch[mid] < g) lo = mid + 1; else hi = mid; }
    int s0 = lo;
    hi = Nn;
    while (lo < hi) { int mid = (lo + hi) >> 1; if (batch[mid] < g + 1) lo = mid + 1; else hi = mid; }
    int s1 = lo;

    float sum0 = 0.f, sum1 = 0.f, sum2 = 0.f, sum3 = 0.f;
    int n = s0;
    for (; n + 4 <= s1; n += 4) {
        sum0 += g_buf1[(size_t)(n + 0) * GD + c];
        sum1 += g_buf1[(size_t)(n + 1) * GD + c];
        sum2 += g_buf1[(size_t)(n + 2) * GD + c];
        sum3 += g_buf1[(size_t)(n + 3) * GD + c];
    }
    for (; n < s1; n++) sum0 += g_buf1[(size_t)n * GD + c];
    float sum = (sum0 + sum1) + (sum2 + sum3);
    float cnt = (float)(s1 - s0);
    out[g * GD + c] = sum / fmaxf(cnt, 1.0f);
}

// -------------------- launch --------------------
extern "C" void kernel_launch(void* const* d_in, const int* in_sizes, int n_in,
                              void* d_out, int out_size) {
    const float* x     = (const float*)d_in[0];
    const int*   ei    = (const int*)d_in[1];
    const int*   batch = (const int*)d_in[2];
    const int Nn = in_sizes[0] / GD;
    const int E  = in_sizes[1] / 2;
    float* out = (float*)d_out;

    static int smem_set = 0;
    if (!smem_set) {
        cudaFuncSetAttribute(gemm_mma, cudaFuncAttributeMaxDynamicSharedMemorySize, GEMM_SMEM_BYTES);
        smem_set = 1;
    }

    // ---- CSR build (by dst) ----
    hist_init<<<(Nn + 255) / 256, 256>>>(Nn);
    hist_edges<<<(E + 255) / 256, 256>>>(ei, E);
    int nb = (Nn + 1023) / 1024;
    scan_block<<<nb, 1024>>>(Nn);
    scan_sums<<<1, 128>>>(nb);
    scan_apply<<<nb, 1024>>>(Nn);
    csr_fill<<<(E + Nn + 255) / 256, 256>>>(ei, E, Nn);

    // ---- 3 GAT layers ----
    int gemm_blocks = (Nn + 63) / 64;
    int warp_blocks = (Nn + 7) / 8;   // 1 warp per node, 256 threads/block
    for (int l = 0; l < 3; l++) {
        const float* W  = (const float*)d_in[3 + 4 * l];
        const float* as = (const float*)d_in[4 + 4 * l];
        const float* ad = (const float*)d_in[5 + 4 * l];
        const float* b  = (const float*)d_in[6 + 4 * l];
        gemm_mma<<<gemm_blocks, 256, GEMM_SMEM_BYTES>>>(x, W, as, ad, l, Nn);
        aggregate<<<warp_blocks, 256>>>(b, l, Nn);
    }

    // ---- mean pool (layer-3 output lives in g_buf1) ----
    pool_kernel<<<NGRAPH, GD>>>(batch, out, Nn);
}

// round 11
// speedup vs baseline: 1.5903x; 1.0585x over previous
#include <cuda_runtime.h>
#include <cuda_bf16.h>
#include <cuda_fp16.h>
#include <cstdint>

// Problem constants (match reference)
#define NN      100000      // nodes
#define EE      800000      // edges (pre self-loop)
#define EPMAX   (EE + NN)   // edges + self loops
#define GD      128         // feature dim
#define NGRAPH  256

#define PK32    68                        // padded K stride in u32 units (136 bf16)
#define A32     (64 * PK32)               // 4352 u32 per A tile
#define B32     (128 * PK32)              // 8704 u32 per B tile
#define ATTN_OFF (2 * A32 + 2 * B32)      // 26112
#define GEMM_SMEM_BYTES ((ATTN_OFF + 768) * 4)   // 107520 bytes -> 2 CTAs/SM

// -------------------- device scratch (no allocs allowed) --------------------
__device__ __half g_bufHh[NN * GD]; // h = in @ W  (fp16 gather source)
__device__ float g_buf1[NN * GD];   // layer outputs (ping)
__device__ float g_buf2[NN * GD];   // layer outputs (pong)
__device__ float g_as[NN];
__device__ float g_ad[NN];
__device__ int   g_deg[NN];         // in-degree (incl self loop)
__device__ int   g_incl[NN];        // per-block inclusive scan
__device__ int   g_bsum[256];       // block sums
__device__ int   g_start[NN];       // CSR row offsets (exclusive scan)
__device__ int   g_cursor[NN];      // fill cursors
__device__ int   g_csr[EPMAX];      // src node id per (dst-sorted) edge
__device__ uint32_t g_Wh[3][B32];   // pre-split W hi (padded B-tile layout)
__device__ uint32_t g_Wl[3][B32];   // pre-split W lo

// -------------------- helpers --------------------
__device__ __forceinline__ void mma16816(float* c, const uint32_t* a, const uint32_t* b) {
    asm volatile(
        "mma.sync.aligned.m16n8k16.row.col.f32.bf16.bf16.f32 "
        "{%0,%1,%2,%3}, {%4,%5,%6,%7}, {%8,%9}, {%0,%1,%2,%3};"
        : "+f"(c[0]), "+f"(c[1]), "+f"(c[2]), "+f"(c[3])
        : "r"(a[0]), "r"(a[1]), "r"(a[2]), "r"(a[3]), "r"(b[0]), "r"(b[1]));
}

__device__ __forceinline__ uint32_t pack_hi(float x, float y, uint32_t& lo) {
    __nv_bfloat16 hx = __float2bfloat16(x);
    __nv_bfloat16 hy = __float2bfloat16(y);
    __nv_bfloat16 lx = __float2bfloat16(x - __bfloat162float(hx));
    __nv_bfloat16 ly = __float2bfloat16(y - __bfloat162float(hy));
    __nv_bfloat162 hp; hp.x = hx; hp.y = hy;
    __nv_bfloat162 lp; lp.x = lx; lp.y = ly;
    lo = *(uint32_t*)&lp;
    return *(uint32_t*)&hp;
}

// -------------------- CSR build (R6-proven form) --------------------
__global__ void hist_init(int Nn) {
    int i = blockIdx.x * blockDim.x + threadIdx.x;
    if (i < Nn) g_deg[i] = 1;   // self loop
}

__global__ void hist_edges(const int* __restrict__ ei, int E) {
    int e = blockIdx.x * blockDim.x + threadIdx.x;
    if (e < E) atomicAdd(&g_deg[ei[E + e]], 1);
}

__global__ void scan_block(int Nn) {
    __shared__ int sm[1024];
    int tid = threadIdx.x;
    int i = blockIdx.x * 1024 + tid;
    int v = (i < Nn) ? g_deg[i] : 0;
    sm[tid] = v;
    __syncthreads();
    #pragma unroll
    for (int off = 1; off < 1024; off <<= 1) {
        int t = (tid >= off) ? sm[tid - off] : 0;
        __syncthreads();
        sm[tid] += t;
        __syncthreads();
    }
    if (i < Nn) g_incl[i] = sm[tid];
    if (tid == 1023) g_bsum[blockIdx.x] = sm[1023];
}

__global__ void scan_sums(int nb) {
    __shared__ int sm[128];
    int t = threadIdx.x;
    int v = (t < nb) ? g_bsum[t] : 0;
    sm[t] = v;
    __syncthreads();
    #pragma unroll
    for (int off = 1; off < 128; off <<= 1) {
        int u = (t >= off) ? sm[t - off] : 0;
        __syncthreads();
        sm[t] += u;
        __syncthreads();
    }
    if (t < nb) g_bsum[t] = sm[t] - v;   // exclusive
}

__global__ void scan_apply(int Nn) {
    int i = blockIdx.x * 1024 + threadIdx.x;
    if (i < Nn) {
        int st = g_incl[i] - g_deg[i] + g_bsum[blockIdx.x];  // exclusive
        g_start[i]  = st;
        g_cursor[i] = st;
    }
}

__global__ void csr_fill(const int* __restrict__ ei, int E, int Nn) {
    int e = blockIdx.x * blockDim.x + threadIdx.x;
    int total = E + Nn;
    if (e >= total) return;
    int s, d;
    if (e < E) { s = ei[e]; d = ei[E + e]; }
    else       { s = d = e - E; }
    int idx = atomicAdd(&g_cursor[d], 1);
    g_csr[idx] = s;
}

// -------------------- W pre-split: fp32 -> bf16 hi/lo in padded B-tile layout --------------------
__global__ void wsplit(const float* __restrict__ W0, const float* __restrict__ W1,
                       const float* __restrict__ W2) {
    int l = blockIdx.x;
    const float* W = (l == 0) ? W0 : ((l == 1) ? W1 : W2);
    int tid = threadIdx.x;
    #pragma unroll
    for (int i = 0; i < 32; i++) {
        int idx = i * 256 + tid;       // 0..8191
        int n   = idx & 127;
        int kp  = idx >> 7;            // 0..63
        float a = W[(size_t)(2 * kp) * GD + n];
        float b = W[(size_t)(2 * kp + 1) * GD + n];
        uint32_t lo, hi = pack_hi(a, b, lo);
        g_Wh[l][n * PK32 + kp] = hi;
        g_Wl[l][n * PK32 + kp] = lo;
    }
}

// -------------------- mma.sync bf16 GEMM (64-row tiles, 2 CTAs/SM) --------------------
__global__ __launch_bounds__(256, 2) void gemm_mma(const float* __restrict__ Xin,
                                                   const float* __restrict__ a_src,
                                                   const float* __restrict__ a_dst,
                                                   int sel, int M) {
    extern __shared__ uint32_t sm32[];
    uint32_t* As_hi = sm32;
    uint32_t* As_lo = sm32 + A32;
    uint32_t* Bs_hi = sm32 + 2 * A32;
    uint32_t* Bs_lo = sm32 + 2 * A32 + B32;
    float* s_asrc = (float*)(sm32 + ATTN_OFF);
    float* s_adst = s_asrc + 128;
    float* s_ps   = s_asrc + 256;     // [4 wn][64 rows]
    float* s_pd   = s_asrc + 512;     // [4 wn][64 rows]

    const float* X = (sel == 0) ? Xin : ((sel == 1) ? g_buf1 : g_buf2);
    const uint32_t* Wh = g_Wh[sel];
    const uint32_t* Wl = g_Wl[sel];
    const int tid  = threadIdx.x;
    const int wid  = tid >> 5;
    const int lane = tid & 31;
    const int m0   = blockIdx.x * 64;

    if (tid < 128) {
        s_asrc[tid] = __ldg(a_src + tid);
        s_adst[tid] = __ldg(a_dst + tid);
    }

    // ---- fill A tile (X rows m0..m0+63), split hi/lo: 4096 u32, 16 iters ----
    #pragma unroll
    for (int i = 0; i < 16; i++) {
        int idx = i * 256 + tid;       // 0..4095
        int r   = idx >> 6;            // 0..63
        int c2  = idx & 63;            // u32 col
        float ax = 0.f, ay = 0.f;
        if (m0 + r < M) {
            float2 v = *(const float2*)(X + (size_t)(m0 + r) * GD + 2 * c2);
            ax = v.x; ay = v.y;
        }
        uint32_t lo, hi = pack_hi(ax, ay, lo);
        As_hi[r * PK32 + c2] = hi;
        As_lo[r * PK32 + c2] = lo;
    }
    // ---- fill B tile: linear copy of pre-split W (B32 = 8704 = 34*256) ----
    #pragma unroll
    for (int i = 0; i < 34; i++) {
        int idx = i * 256 + tid;
        Bs_hi[idx] = Wh[idx];
        Bs_lo[idx] = Wl[idx];
    }
    __syncthreads();

    // ---- warp tiling: 2x4 warps, warp tile 32x32 ----
    const int wm = wid & 1;            // m group (32 rows)
    const int wn = wid >> 1;           // n group (32 cols), 0..3
    const int g  = lane >> 2;
    const int t  = lane & 3;

    float acc[2][4][4];
    #pragma unroll
    for (int mt = 0; mt < 2; mt++)
        #pragma unroll
        for (int nt = 0; nt < 4; nt++)
            #pragma unroll
            for (int q = 0; q < 4; q++) acc[mt][nt][q] = 0.f;

    #pragma unroll
    for (int ks = 0; ks < 8; ks++) {       // k0 = ks*16, u32 offset = ks*8
        const int kb = ks * 8 + t;
        uint32_t ah[2][4], al[2][4];
        #pragma unroll
        for (int mt = 0; mt < 2; mt++) {
            int R = wm * 32 + mt * 16 + g;
            ah[mt][0] = As_hi[R * PK32 + kb];
            ah[mt][1] = As_hi[(R + 8) * PK32 + kb];
            ah[mt][2] = As_hi[R * PK32 + kb + 4];
            ah[mt][3] = As_hi[(R + 8) * PK32 + kb + 4];
            al[mt][0] = As_lo[R * PK32 + kb];
            al[mt][1] = As_lo[(R + 8) * PK32 + kb];
            al[mt][2] = As_lo[R * PK32 + kb + 4];
            al[mt][3] = As_lo[(R + 8) * PK32 + kb + 4];
        }
        uint32_t bh[4][2], bl[4][2];
        #pragma unroll
        for (int nt = 0; nt < 4; nt++) {
            int C = wn * 32 + nt * 8 + g;
            bh[nt][0] = Bs_hi[C * PK32 + kb];
            bh[nt][1] = Bs_hi[C * PK32 + kb + 4];
            bl[nt][0] = Bs_lo[C * PK32 + kb];
            bl[nt][1] = Bs_lo[C * PK32 + kb + 4];
        }
        #pragma unroll
        for (int mt = 0; mt < 2; mt++)
            #pragma unroll
            for (int nt = 0; nt < 4; nt++) {
                mma16816(acc[mt][nt], ah[mt], bh[nt]);
                mma16816(acc[mt][nt], al[mt], bh[nt]);
                mma16816(acc[mt][nt], ah[mt], bl[nt]);
            }
    }

    // ---- epilogue: write fp16 h + fused attention dot products ----
    float ps[4] = {0.f, 0.f, 0.f, 0.f};   // q = mt*2 + half
    float pd[4] = {0.f, 0.f, 0.f, 0.f};
    #pragma unroll
    for (int mt = 0; mt < 2; mt++) {
        int r0 = m0 + wm * 32 + mt * 16 + g;
        #pragma unroll
        for (int nt = 0; nt < 4; nt++) {
            int cc = wn * 32 + nt * 8 + 2 * t;
            float a0 = s_asrc[cc], a1 = s_asrc[cc + 1];
            float d0 = s_adst[cc], d1 = s_adst[cc + 1];
            ps[mt * 2 + 0] += acc[mt][nt][0] * a0 + acc[mt][nt][1] * a1;
            ps[mt * 2 + 1] += acc[mt][nt][2] * a0 + acc[mt][nt][3] * a1;
            pd[mt * 2 + 0] += acc[mt][nt][0] * d0 + acc[mt][nt][1] * d1;
            pd[mt * 2 + 1] += acc[mt][nt][2] * d0 + acc[mt][nt][3] * d1;
            if (r0 < M)
                *(__half2*)(g_bufHh + (size_t)r0 * GD + cc) =
                    __floats2half2_rn(acc[mt][nt][0], acc[mt][nt][1]);
            if (r0 + 8 < M)
                *(__half2*)(g_bufHh + (size_t)(r0 + 8) * GD + cc) =
                    __floats2half2_rn(acc[mt][nt][2], acc[mt][nt][3]);
        }
    }
    #pragma unroll
    for (int q = 0; q < 4; q++) {
        ps[q] += __shfl_xor_sync(0xFFFFFFFFu, ps[q], 1);
        ps[q] += __shfl_xor_sync(0xFFFFFFFFu, ps[q], 2);
        pd[q] += __shfl_xor_sync(0xFFFFFFFFu, pd[q], 1);
        pd[q] += __shfl_xor_sync(0xFFFFFFFFu, pd[q], 2);
    }
    if (t == 0) {
        #pragma unroll
        for (int q = 0; q < 4; q++) {
            int local = wm * 32 + (q >> 1) * 16 + (q & 1) * 8 + g;
            s_ps[wn * 64 + local] = ps[q];
            s_pd[wn * 64 + local] = pd[q];
        }
    }
    __syncthreads();
    if (tid < 64) {
        int m = m0 + tid;
        if (m < M) {
            g_as[m] = (s_ps[tid] + s_ps[64 + tid]) + (s_ps[128 + tid] + s_ps[192 + tid]);
            g_ad[m] = (s_pd[tid] + s_pd[64 + tid]) + (s_pd[128 + tid] + s_pd[192 + tid]);
        }
    }
}

// -------------------- fused softmax + aggregate + bias (warp per dst) --------------------
__global__ void aggregate(const float* __restrict__ bias, int sel, int Nn) {
    int d = (blockIdx.x * blockDim.x + threadIdx.x) >> 5;
    int lane = threadIdx.x & 31;
    if (d >= Nn) return;
    float* OUT = (sel == 1) ? g_buf2 : g_buf1;   // 0->buf1, 1->buf2, 2->buf1

    int beg = g_start[d];
    int end = beg + g_deg[d];
    float adv = g_ad[d];

    // pass 1: max logit (lanes parallel over edges)
    float mx = -3.0e38f;
    for (int i = beg + lane; i < end; i += 32) {
        float l = g_as[g_csr[i]] + adv;
        l = l > 0.0f ? l : 0.2f * l;
        mx = fmaxf(mx, l);
    }
    #pragma unroll
    for (int off = 16; off; off >>= 1)
        mx = fmaxf(mx, __shfl_xor_sync(0xFFFFFFFFu, mx, off));

    // pass 2: exp, denom, weighted fp16 gather-accumulate (4-way unrolled for MLP)
    float denom = 0.0f;
    float4 acc = make_float4(0.f, 0.f, 0.f, 0.f);
    int i = beg;
    for (; i + 4 <= end; i += 4) {
        int s0 = g_csr[i], s1 = g_csr[i + 1], s2 = g_csr[i + 2], s3 = g_csr[i + 3];
        float l0 = g_as[s0] + adv;
        float l1 = g_as[s1] + adv;
        float l2 = g_as[s2] + adv;
        float l3 = g_as[s3] + adv;
        uint2 r0 = *(const uint2*)(g_bufHh + (size_t)s0 * GD + lane * 4);
        uint2 r1 = *(const uint2*)(g_bufHh + (size_t)s1 * GD + lane * 4);
        uint2 r2 = *(const uint2*)(g_bufHh + (size_t)s2 * GD + lane * 4);
        uint2 r3 = *(const uint2*)(g_bufHh + (size_t)s3 * GD + lane * 4);
        l0 = l0 > 0.0f ? l0 : 0.2f * l0;
        l1 = l1 > 0.0f ? l1 : 0.2f * l1;
        l2 = l2 > 0.0f ? l2 : 0.2f * l2;
        l3 = l3 > 0.0f ? l3 : 0.2f * l3;
        float v0 = __expf(l0 - mx);
        float v1 = __expf(l1 - mx);
        float v2 = __expf(l2 - mx);
        float v3 = __expf(l3 - mx);
        denom += (v0 + v1) + (v2 + v3);
        float2 a0 = __half22float2(*(__half2*)&r0.x);
        float2 a1 = __half22float2(*(__half2*)&r0.y);
        float2 b0 = __half22float2(*(__half2*)&r1.x);
        float2 b1 = __half22float2(*(__half2*)&r1.y);
        float2 c0 = __half22float2(*(__half2*)&r2.x);
        float2 c1 = __half22float2(*(__half2*)&r2.y);
        float2 e0 = __half22float2(*(__half2*)&r3.x);
        float2 e1 = __half22float2(*(__half2*)&r3.y);
        acc.x = fmaf(v0, a0.x, acc.x); acc.x = fmaf(v1, b0.x, acc.x);
        acc.x = fmaf(v2, c0.x, acc.x); acc.x = fmaf(v3, e0.x, acc.x);
        acc.y = fmaf(v0, a0.y, acc.y); acc.y = fmaf(v1, b0.y, acc.y);
        acc.y = fmaf(v2, c0.y, acc.y); acc.y = fmaf(v3, e0.y, acc.y);
        acc.z = fmaf(v0, a1.x, acc.z); acc.z = fmaf(v1, b1.x, acc.z);
        acc.z = fmaf(v2, c1.x, acc.z); acc.z = fmaf(v3, e1.x, acc.z);
        acc.w = fmaf(v0, a1.y, acc.w); acc.w = fmaf(v1, b1.y, acc.w);
        acc.w = fmaf(v2, c1.y, acc.w); acc.w = fmaf(v3, e1.y, acc.w);
    }
    for (; i < end; i++) {
        int s = g_csr[i];
        float l = g_as[s] + adv;
        l = l > 0.0f ? l : 0.2f * l;
        float v = __expf(l - mx);
        uint2 r = *(const uint2*)(g_bufHh + (size_t)s * GD + lane * 4);
        denom += v;
        float2 a0 = __half22float2(*(__half2*)&r.x);
        float2 a1 = __half22float2(*(__half2*)&r.y);
        acc.x = fmaf(v, a0.x, acc.x);
        acc.y = fmaf(v, a0.y, acc.y);
        acc.z = fmaf(v, a1.x, acc.z);
        acc.w = fmaf(v, a1.y, acc.w);
    }
    float inv = 1.0f / denom;
    float4 b4 = __ldg(((const float4*)bias) + lane);
    float4 o = make_float4(acc.x * inv + b4.x, acc.y * inv + b4.y,
                           acc.z * inv + b4.z, acc.w * inv + b4.w);
    ((float4*)OUT)[(size_t)d * 32 + lane] = o;
}

// -------------------- global mean pool (block per graph, sorted batch) --------------------
__global__ void pool_kernel(const int* __restrict__ batch, float* __restrict__ out, int Nn) {
    int g = blockIdx.x;        // 0..255
    int c = threadIdx.x;       // 0..127
    int lo = 0, hi = Nn;
    while (lo < hi) { int mid = (lo + hi) >> 1; if (batch[mid] < g) lo = mid + 1; else hi = mid; }
    int s0 = lo;
    hi = Nn;
    while (lo < hi) { int mid = (lo + hi) >> 1; if (batch[mid] < g + 1) lo = mid + 1; else hi = mid; }
    int s1 = lo;

    float sum0 = 0.f, sum1 = 0.f, sum2 = 0.f, sum3 = 0.f;
    int n = s0;
    for (; n + 4 <= s1; n += 4) {
        sum0 += g_buf1[(size_t)(n + 0) * GD + c];
        sum1 += g_buf1[(size_t)(n + 1) * GD + c];
        sum2 += g_buf1[(size_t)(n + 2) * GD + c];
        sum3 += g_buf1[(size_t)(n + 3) * GD + c];
    }
    for (; n < s1; n++) sum0 += g_buf1[(size_t)n * GD + c];
    float sum = (sum0 + sum1) + (sum2 + sum3);
    float cnt = (float)(s1 - s0);
    out[g * GD + c] = sum / fmaxf(cnt, 1.0f);
}

// -------------------- launch --------------------
extern "C" void kernel_launch(void* const* d_in, const int* in_sizes, int n_in,
                              void* d_out, int out_size) {
    const float* x     = (const float*)d_in[0];
    const int*   ei    = (const int*)d_in[1];
    const int*   batch = (const int*)d_in[2];
    const int Nn = in_sizes[0] / GD;
    const int E  = in_sizes[1] / 2;
    float* out = (float*)d_out;

    static int smem_set = 0;
    if (!smem_set) {
        cudaFuncSetAttribute(gemm_mma, cudaFuncAttributeMaxDynamicSharedMemorySize, GEMM_SMEM_BYTES);
        smem_set = 1;
    }

    // ---- W pre-split (overlaps CSR build region) ----
    wsplit<<<3, 256>>>((const float*)d_in[3], (const float*)d_in[7], (const float*)d_in[11]);

    // ---- CSR build (by dst) ----
    hist_init<<<(Nn + 255) / 256, 256>>>(Nn);
    hist_edges<<<(E + 255) / 256, 256>>>(ei, E);
    int nb = (Nn + 1023) / 1024;
    scan_block<<<nb, 1024>>>(Nn);
    scan_sums<<<1, 128>>>(nb);
    scan_apply<<<nb, 1024>>>(Nn);
    csr_fill<<<(E + Nn + 255) / 256, 256>>>(ei, E, Nn);

    // ---- 3 GAT layers ----
    int gemm_blocks = (Nn + 63) / 64;
    int warp_blocks = (Nn + 7) / 8;   // 1 warp per node, 256 threads/block
    for (int l = 0; l < 3; l++) {
        const float* as = (const float*)d_in[4 + 4 * l];
        const float* ad = (const float*)d_in[5 + 4 * l];
        const float* b  = (const float*)d_in[6 + 4 * l];
        gemm_mma<<<gemm_blocks, 256, GEMM_SMEM_BYTES>>>(x, as, ad, l, Nn);
        aggregate<<<warp_blocks, 256>>>(b, l, Nn);
    }

    // ---- mean pool (layer-3 output lives in g_buf1) ----
    pool_kernel<<<NGRAPH, GD>>>(batch, out, Nn);
}

// round 12
// speedup vs baseline: 1.6334x; 1.0271x over previous
#include <cuda_runtime.h>
#include <cuda_bf16.h>
#include <cuda_fp16.h>
#include <cstdint>

// Problem constants (match reference)
#define NN      100000      // nodes
#define EE      800000      // edges (pre self-loop)
#define EPMAX   (EE + NN)   // edges + self loops
#define GD      128         // feature dim
#define NGRAPH  256

#define PK32    68                        // padded K stride in u32 units (136 bf16)
#define A32     (64 * PK32)               // 4352 u32 per A tile
#define B32     (128 * PK32)              // 8704 u32 per B tile
#define ATTN_OFF (2 * A32 + 2 * B32)      // 26112
#define GEMM_SMEM_BYTES ((ATTN_OFF + 768) * 4)   // 107520 bytes -> 2 CTAs/SM

// -------------------- device scratch (no allocs allowed) --------------------
__device__ __half g_bufHh[NN * GD]; // h = in @ W  (fp16 gather source)
__device__ float g_buf1[NN * GD];   // layer outputs (ping)
__device__ float g_buf2[NN * GD];   // layer outputs (pong)
__device__ float g_as[NN];
__device__ float g_ad[NN];
__device__ int   g_deg[NN];         // in-degree (incl self loop)
__device__ int   g_incl[NN];        // per-block inclusive scan
__device__ int   g_bsum[256];       // block sums
__device__ int   g_start[NN];       // CSR row offsets (exclusive scan)
__device__ int   g_cursor[NN];      // fill cursors
__device__ int   g_csr[EPMAX];      // src node id per (dst-sorted) edge
__device__ uint32_t g_Wh[3][B32];   // pre-split W hi (padded B-tile layout)
__device__ uint32_t g_Wl[3][B32];   // pre-split W lo

// -------------------- helpers --------------------
__device__ __forceinline__ void mma16816(float* c, const uint32_t* a, const uint32_t* b) {
    asm volatile(
        "mma.sync.aligned.m16n8k16.row.col.f32.bf16.bf16.f32 "
        "{%0,%1,%2,%3}, {%4,%5,%6,%7}, {%8,%9}, {%0,%1,%2,%3};"
        : "+f"(c[0]), "+f"(c[1]), "+f"(c[2]), "+f"(c[3])
        : "r"(a[0]), "r"(a[1]), "r"(a[2]), "r"(a[3]), "r"(b[0]), "r"(b[1]));
}

__device__ __forceinline__ uint32_t pack_hi(float x, float y, uint32_t& lo) {
    __nv_bfloat16 hx = __float2bfloat16(x);
    __nv_bfloat16 hy = __float2bfloat16(y);
    __nv_bfloat16 lx = __float2bfloat16(x - __bfloat162float(hx));
    __nv_bfloat16 ly = __float2bfloat16(y - __bfloat162float(hy));
    __nv_bfloat162 hp; hp.x = hx; hp.y = hy;
    __nv_bfloat162 lp; lp.x = lx; lp.y = ly;
    lo = *(uint32_t*)&lp;
    return *(uint32_t*)&hp;
}

// -------------------- CSR build (R6-proven form) --------------------
__global__ void hist_init(int Nn) {
    int i = blockIdx.x * blockDim.x + threadIdx.x;
    if (i < Nn) g_deg[i] = 1;   // self loop
}

__global__ void hist_edges(const int* __restrict__ ei, int E) {
    int e = blockIdx.x * blockDim.x + threadIdx.x;
    if (e < E) atomicAdd(&g_deg[ei[E + e]], 1);
}

__global__ void scan_block(int Nn) {
    __shared__ int sm[1024];
    int tid = threadIdx.x;
    int i = blockIdx.x * 1024 + tid;
    int v = (i < Nn) ? g_deg[i] : 0;
    sm[tid] = v;
    __syncthreads();
    #pragma unroll
    for (int off = 1; off < 1024; off <<= 1) {
        int t = (tid >= off) ? sm[tid - off] : 0;
        __syncthreads();
        sm[tid] += t;
        __syncthreads();
    }
    if (i < Nn) g_incl[i] = sm[tid];
    if (tid == 1023) g_bsum[blockIdx.x] = sm[1023];
}

__global__ void scan_sums(int nb) {
    __shared__ int sm[128];
    int t = threadIdx.x;
    int v = (t < nb) ? g_bsum[t] : 0;
    sm[t] = v;
    __syncthreads();
    #pragma unroll
    for (int off = 1; off < 128; off <<= 1) {
        int u = (t >= off) ? sm[t - off] : 0;
        __syncthreads();
        sm[t] += u;
        __syncthreads();
    }
    if (t < nb) g_bsum[t] = sm[t] - v;   // exclusive
}

__global__ void scan_apply(int Nn) {
    int i = blockIdx.x * 1024 + threadIdx.x;
    if (i < Nn) {
        int st = g_incl[i] - g_deg[i] + g_bsum[blockIdx.x];  // exclusive
        g_start[i]  = st;
        g_cursor[i] = st;
    }
}

__global__ void csr_fill(const int* __restrict__ ei, int E, int Nn) {
    int e = blockIdx.x * blockDim.x + threadIdx.x;
    int total = E + Nn;
    if (e >= total) return;
    int s, d;
    if (e < E) { s = ei[e]; d = ei[E + e]; }
    else       { s = d = e - E; }
    int idx = atomicAdd(&g_cursor[d], 1);
    g_csr[idx] = s;
}

// -------------------- W pre-split: fp32 -> bf16 hi/lo in padded B-tile layout --------------------
__global__ void wsplit(const float* __restrict__ W0, const float* __restrict__ W1,
                       const float* __restrict__ W2) {
    int l = blockIdx.x;
    const float* W = (l == 0) ? W0 : ((l == 1) ? W1 : W2);
    int tid = threadIdx.x;
    #pragma unroll
    for (int i = 0; i < 32; i++) {
        int idx = i * 256 + tid;       // 0..8191
        int n   = idx & 127;
        int kp  = idx >> 7;            // 0..63
        float a = W[(size_t)(2 * kp) * GD + n];
        float b = W[(size_t)(2 * kp + 1) * GD + n];
        uint32_t lo, hi = pack_hi(a, b, lo);
        g_Wh[l][n * PK32 + kp] = hi;
        g_Wl[l][n * PK32 + kp] = lo;
    }
}

// -------------------- mma.sync bf16 GEMM (64-row tiles, 2 CTAs/SM) --------------------
__global__ __launch_bounds__(256, 2) void gemm_mma(const float* __restrict__ Xin,
                                                   const float* __restrict__ a_src,
                                                   const float* __restrict__ a_dst,
                                                   int sel, int M) {
    extern __shared__ uint32_t sm32[];
    uint32_t* As_hi = sm32;
    uint32_t* As_lo = sm32 + A32;
    uint32_t* Bs_hi = sm32 + 2 * A32;
    uint32_t* Bs_lo = sm32 + 2 * A32 + B32;
    float* s_asrc = (float*)(sm32 + ATTN_OFF);
    float* s_adst = s_asrc + 128;
    float* s_ps   = s_asrc + 256;     // [4 wn][64 rows]
    float* s_pd   = s_asrc + 512;     // [4 wn][64 rows]

    const float* X = (sel == 0) ? Xin : ((sel == 1) ? g_buf1 : g_buf2);
    const uint32_t* Wh = g_Wh[sel];
    const uint32_t* Wl = g_Wl[sel];
    const int tid  = threadIdx.x;
    const int wid  = tid >> 5;
    const int lane = tid & 31;
    const int m0   = blockIdx.x * 64;

    if (tid < 128) {
        s_asrc[tid] = __ldg(a_src + tid);
        s_adst[tid] = __ldg(a_dst + tid);
    }

    // ---- fill A tile (X rows m0..m0+63), split hi/lo: 4096 u32, 16 iters ----
    #pragma unroll
    for (int i = 0; i < 16; i++) {
        int idx = i * 256 + tid;       // 0..4095
        int r   = idx >> 6;            // 0..63
        int c2  = idx & 63;            // u32 col
        float ax = 0.f, ay = 0.f;
        if (m0 + r < M) {
            float2 v = *(const float2*)(X + (size_t)(m0 + r) * GD + 2 * c2);
            ax = v.x; ay = v.y;
        }
        uint32_t lo, hi = pack_hi(ax, ay, lo);
        As_hi[r * PK32 + c2] = hi;
        As_lo[r * PK32 + c2] = lo;
    }
    // ---- fill B tile: linear copy of pre-split W (B32 = 8704 = 34*256) ----
    #pragma unroll
    for (int i = 0; i < 34; i++) {
        int idx = i * 256 + tid;
        Bs_hi[idx] = Wh[idx];
        Bs_lo[idx] = Wl[idx];
    }
    __syncthreads();

    // ---- warp tiling: 2x4 warps, warp tile 32x32 ----
    const int wm = wid & 1;            // m group (32 rows)
    const int wn = wid >> 1;           // n group (32 cols), 0..3
    const int g  = lane >> 2;
    const int t  = lane & 3;

    float acc[2][4][4];
    #pragma unroll
    for (int mt = 0; mt < 2; mt++)
        #pragma unroll
        for (int nt = 0; nt < 4; nt++)
            #pragma unroll
            for (int q = 0; q < 4; q++) acc[mt][nt][q] = 0.f;

    #pragma unroll
    for (int ks = 0; ks < 8; ks++) {       // k0 = ks*16, u32 offset = ks*8
        const int kb = ks * 8 + t;
        uint32_t ah[2][4], al[2][4];
        #pragma unroll
        for (int mt = 0; mt < 2; mt++) {
            int R = wm * 32 + mt * 16 + g;
            ah[mt][0] = As_hi[R * PK32 + kb];
            ah[mt][1] = As_hi[(R + 8) * PK32 + kb];
            ah[mt][2] = As_hi[R * PK32 + kb + 4];
            ah[mt][3] = As_hi[(R + 8) * PK32 + kb + 4];
            al[mt][0] = As_lo[R * PK32 + kb];
            al[mt][1] = As_lo[(R + 8) * PK32 + kb];
            al[mt][2] = As_lo[R * PK32 + kb + 4];
            al[mt][3] = As_lo[(R + 8) * PK32 + kb + 4];
        }
        uint32_t bh[4][2], bl[4][2];
        #pragma unroll
        for (int nt = 0; nt < 4; nt++) {
            int C = wn * 32 + nt * 8 + g;
            bh[nt][0] = Bs_hi[C * PK32 + kb];
            bh[nt][1] = Bs_hi[C * PK32 + kb + 4];
            bl[nt][0] = Bs_lo[C * PK32 + kb];
            bl[nt][1] = Bs_lo[C * PK32 + kb + 4];
        }
        #pragma unroll
        for (int mt = 0; mt < 2; mt++)
            #pragma unroll
            for (int nt = 0; nt < 4; nt++) {
                mma16816(acc[mt][nt], ah[mt], bh[nt]);
                mma16816(acc[mt][nt], al[mt], bh[nt]);
                mma16816(acc[mt][nt], ah[mt], bl[nt]);
            }
    }

    // ---- epilogue: write fp16 h + fused attention dot products ----
    float ps[4] = {0.f, 0.f, 0.f, 0.f};   // q = mt*2 + half
    float pd[4] = {0.f, 0.f, 0.f, 0.f};
    #pragma unroll
    for (int mt = 0; mt < 2; mt++) {
        int r0 = m0 + wm * 32 + mt * 16 + g;
        #pragma unroll
        for (int nt = 0; nt < 4; nt++) {
            int cc = wn * 32 + nt * 8 + 2 * t;
            float a0 = s_asrc[cc], a1 = s_asrc[cc + 1];
            float d0 = s_adst[cc], d1 = s_adst[cc + 1];
            ps[mt * 2 + 0] += acc[mt][nt][0] * a0 + acc[mt][nt][1] * a1;
            ps[mt * 2 + 1] += acc[mt][nt][2] * a0 + acc[mt][nt][3] * a1;
            pd[mt * 2 + 0] += acc[mt][nt][0] * d0 + acc[mt][nt][1] * d1;
            pd[mt * 2 + 1] += acc[mt][nt][2] * d0 + acc[mt][nt][3] * d1;
            if (r0 < M)
                *(__half2*)(g_bufHh + (size_t)r0 * GD + cc) =
                    __floats2half2_rn(acc[mt][nt][0], acc[mt][nt][1]);
            if (r0 + 8 < M)
                *(__half2*)(g_bufHh + (size_t)(r0 + 8) * GD + cc) =
                    __floats2half2_rn(acc[mt][nt][2], acc[mt][nt][3]);
        }
    }
    #pragma unroll
    for (int q = 0; q < 4; q++) {
        ps[q] += __shfl_xor_sync(0xFFFFFFFFu, ps[q], 1);
        ps[q] += __shfl_xor_sync(0xFFFFFFFFu, ps[q], 2);
        pd[q] += __shfl_xor_sync(0xFFFFFFFFu, pd[q], 1);
        pd[q] += __shfl_xor_sync(0xFFFFFFFFu, pd[q], 2);
    }
    if (t == 0) {
        #pragma unroll
        for (int q = 0; q < 4; q++) {
            int local = wm * 32 + (q >> 1) * 16 + (q & 1) * 8 + g;
            s_ps[wn * 64 + local] = ps[q];
            s_pd[wn * 64 + local] = pd[q];
        }
    }
    __syncthreads();
    if (tid < 64) {
        int m = m0 + tid;
        if (m < M) {
            g_as[m] = (s_ps[tid] + s_ps[64 + tid]) + (s_ps[128 + tid] + s_ps[192 + tid]);
            g_ad[m] = (s_pd[tid] + s_pd[64 + tid]) + (s_pd[128 + tid] + s_pd[192 + tid]);
        }
    }
}

// -------------------- fused softmax + aggregate + bias (warp per dst) --------------------
__global__ void aggregate(const float* __restrict__ bias, int sel, int Nn) {
    int d = (blockIdx.x * blockDim.x + threadIdx.x) >> 5;
    int lane = threadIdx.x & 31;
    if (d >= Nn) return;
    float* OUT = (sel == 1) ? g_buf2 : g_buf1;   // 0->buf1, 1->buf2, 2->buf1

    int beg = g_start[d];
    int end = beg + g_deg[d];
    float adv = g_ad[d];

    // pass 1: max logit (lanes parallel over edges)
    float mx = -3.0e38f;
    for (int i = beg + lane; i < end; i += 32) {
        float l = g_as[g_csr[i]] + adv;
        l = l > 0.0f ? l : 0.2f * l;
        mx = fmaxf(mx, l);
    }
    #pragma unroll
    for (int off = 16; off; off >>= 1)
        mx = fmaxf(mx, __shfl_xor_sync(0xFFFFFFFFu, mx, off));

    // pass 2: exp, denom, weighted fp16 gather-accumulate (4-way unrolled for MLP)
    float denom = 0.0f;
    float4 acc = make_float4(0.f, 0.f, 0.f, 0.f);
    int i = beg;
    for (; i + 4 <= end; i += 4) {
        int s0 = g_csr[i], s1 = g_csr[i + 1], s2 = g_csr[i + 2], s3 = g_csr[i + 3];
        float l0 = g_as[s0] + adv;
        float l1 = g_as[s1] + adv;
        float l2 = g_as[s2] + adv;
        float l3 = g_as[s3] + adv;
        uint2 r0 = *(const uint2*)(g_bufHh + (size_t)s0 * GD + lane * 4);
        uint2 r1 = *(const uint2*)(g_bufHh + (size_t)s1 * GD + lane * 4);
        uint2 r2 = *(const uint2*)(g_bufHh + (size_t)s2 * GD + lane * 4);
        uint2 r3 = *(const uint2*)(g_bufHh + (size_t)s3 * GD + lane * 4);
        l0 = l0 > 0.0f ? l0 : 0.2f * l0;
        l1 = l1 > 0.0f ? l1 : 0.2f * l1;
        l2 = l2 > 0.0f ? l2 : 0.2f * l2;
        l3 = l3 > 0.0f ? l3 : 0.2f * l3;
        float v0 = __expf(l0 - mx);
        float v1 = __expf(l1 - mx);
        float v2 = __expf(l2 - mx);
        float v3 = __expf(l3 - mx);
        denom += (v0 + v1) + (v2 + v3);
        float2 a0 = __half22float2(*(__half2*)&r0.x);
        float2 a1 = __half22float2(*(__half2*)&r0.y);
        float2 b0 = __half22float2(*(__half2*)&r1.x);
        float2 b1 = __half22float2(*(__half2*)&r1.y);
        float2 c0 = __half22float2(*(__half2*)&r2.x);
        float2 c1 = __half22float2(*(__half2*)&r2.y);
        float2 e0 = __half22float2(*(__half2*)&r3.x);
        float2 e1 = __half22float2(*(__half2*)&r3.y);
        acc.x = fmaf(v0, a0.x, acc.x); acc.x = fmaf(v1, b0.x, acc.x);
        acc.x = fmaf(v2, c0.x, acc.x); acc.x = fmaf(v3, e0.x, acc.x);
        acc.y = fmaf(v0, a0.y, acc.y); acc.y = fmaf(v1, b0.y, acc.y);
        acc.y = fmaf(v2, c0.y, acc.y); acc.y = fmaf(v3, e0.y, acc.y);
        acc.z = fmaf(v0, a1.x, acc.z); acc.z = fmaf(v1, b1.x, acc.z);
        acc.z = fmaf(v2, c1.x, acc.z); acc.z = fmaf(v3, e1.x, acc.z);
        acc.w = fmaf(v0, a1.y, acc.w); acc.w = fmaf(v1, b1.y, acc.w);
        acc.w = fmaf(v2, c1.y, acc.w); acc.w = fmaf(v3, e1.y, acc.w);
    }
    for (; i < end; i++) {
        int s = g_csr[i];
        float l = g_as[s] + adv;
        l = l > 0.0f ? l : 0.2f * l;
        float v = __expf(l - mx);
        uint2 r = *(const uint2*)(g_bufHh + (size_t)s * GD + lane * 4);
        denom += v;
        float2 a0 = __half22float2(*(__half2*)&r.x);
        float2 a1 = __half22float2(*(__half2*)&r.y);
        acc.x = fmaf(v, a0.x, acc.x);
        acc.y = fmaf(v, a0.y, acc.y);
        acc.z = fmaf(v, a1.x, acc.z);
        acc.w = fmaf(v, a1.y, acc.w);
    }
    float inv = 1.0f / denom;
    float4 b4 = __ldg(((const float4*)bias) + lane);
    float4 o = make_float4(acc.x * inv + b4.x, acc.y * inv + b4.y,
                           acc.z * inv + b4.z, acc.w * inv + b4.w);
    ((float4*)OUT)[(size_t)d * 32 + lane] = o;
}

// -------------------- global mean pool (block per graph, sorted batch) --------------------
__global__ void pool_kernel(const int* __restrict__ batch, float* __restrict__ out, int Nn) {
    int g = blockIdx.x;        // 0..255
    int c = threadIdx.x;       // 0..127
    int lo = 0, hi = Nn;
    while (lo < hi) { int mid = (lo + hi) >> 1; if (batch[mid] < g) lo = mid + 1; else hi = mid; }
    int s0 = lo;
    hi = Nn;
    while (lo < hi) { int mid = (lo + hi) >> 1; if (batch[mid] < g + 1) lo = mid + 1; else hi = mid; }
    int s1 = lo;

    float sum0 = 0.f, sum1 = 0.f, sum2 = 0.f, sum3 = 0.f;
    int n = s0;
    for (; n + 4 <= s1; n += 4) {
        sum0 += g_buf1[(size_t)(n + 0) * GD + c];
        sum1 += g_buf1[(size_t)(n + 1) * GD + c];
        sum2 += g_buf1[(size_t)(n + 2) * GD + c];
        sum3 += g_buf1[(size_t)(n + 3) * GD + c];
    }
    for (; n < s1; n++) sum0 += g_buf1[(size_t)n * GD + c];
    float sum = (sum0 + sum1) + (sum2 + sum3);
    float cnt = (float)(s1 - s0);
    out[g * GD + c] = sum / fmaxf(cnt, 1.0f);
}

// -------------------- launch --------------------
extern "C" void kernel_launch(void* const* d_in, const int* in_sizes, int n_in,
                              void* d_out, int out_size) {
    const float* x     = (const float*)d_in[0];
    const int*   ei    = (const int*)d_in[1];
    const int*   batch = (const int*)d_in[2];
    const int Nn = in_sizes[0] / GD;
    const int E  = in_sizes[1] / 2;
    float* out = (float*)d_out;

    static int init_done = 0;
    static cudaStream_t s_csr;
    static cudaEvent_t ev_fork, ev_join;
    if (!init_done) {
        cudaFuncSetAttribute(gemm_mma, cudaFuncAttributeMaxDynamicSharedMemorySize, GEMM_SMEM_BYTES);
        cudaStreamCreateWithFlags(&s_csr, cudaStreamNonBlocking);
        cudaEventCreateWithFlags(&ev_fork, cudaEventDisableTiming);
        cudaEventCreateWithFlags(&ev_join, cudaEventDisableTiming);
        init_done = 1;
    }

    int gemm_blocks = (Nn + 63) / 64;
    int warp_blocks = (Nn + 7) / 8;   // 1 warp per node, 256 threads/block

    // ---- fork: CSR build on side stream, overlapped with wsplit + layer-1 GEMM ----
    cudaEventRecord(ev_fork, 0);
    cudaStreamWaitEvent(s_csr, ev_fork, 0);

    hist_init<<<(Nn + 255) / 256, 256, 0, s_csr>>>(Nn);
    hist_edges<<<(E + 255) / 256, 256, 0, s_csr>>>(ei, E);
    int nb = (Nn + 1023) / 1024;
    scan_block<<<nb, 1024, 0, s_csr>>>(Nn);
    scan_sums<<<1, 128, 0, s_csr>>>(nb);
    scan_apply<<<nb, 1024, 0, s_csr>>>(Nn);
    csr_fill<<<(E + Nn + 255) / 256, 256, 0, s_csr>>>(ei, E, Nn);
    cudaEventRecord(ev_join, s_csr);

    // main stream: weight split + layer-1 GEMM (independent of CSR)
    wsplit<<<3, 256>>>((const float*)d_in[3], (const float*)d_in[7], (const float*)d_in[11]);
    gemm_mma<<<gemm_blocks, 256, GEMM_SMEM_BYTES>>>(
        x, (const float*)d_in[4], (const float*)d_in[5], 0, Nn);

    // join: first aggregate needs the CSR
    cudaStreamWaitEvent(0, ev_join, 0);
    aggregate<<<warp_blocks, 256>>>((const float*)d_in[6], 0, Nn);

    // ---- layers 2 and 3 (serial on main stream) ----
    for (int l = 1; l < 3; l++) {
        const float* as = (const float*)d_in[4 + 4 * l];
        const float* ad = (const float*)d_in[5 + 4 * l];
        const float* b  = (const float*)d_in[6 + 4 * l];
        gemm_mma<<<gemm_blocks, 256, GEMM_SMEM_BYTES>>>(x, as, ad, l, Nn);
        aggregate<<<warp_blocks, 256>>>(b, l, Nn);
    }

    // ---- mean pool (layer-3 output lives in g_buf1) ----
    pool_kernel<<<NGRAPH, GD>>>(batch, out, Nn);
}